// round 2
// baseline (speedup 1.0000x reference)
#include <cuda_runtime.h>

// Problem constants
#define S_DIM  128
#define I_DIM  384
#define IN_D   256
#define PD     32      // PROJ_DIM
#define OD     128     // OUT_DIM
#define IDX    (I_DIM * PD)   // 12288 (i*32+d flattened)

// Scratch (static device globals -- no runtime allocation)
__device__ float g_L[S_DIM * IDX];       // l[s][i*32+d]   6.29 MB
__device__ float g_R[S_DIM * IDX];       // r[s][j*32+e]   6.29 MB
__device__ float g_norm[I_DIM * I_DIM];  // mask Gram      0.59 MB

// ---------------------------------------------------------------------------
// Kernel A: LayerNorm + projection + mask -> g_L, g_R
// One warp per (s,i) row; 8 rows per 256-thread block. W_proj staged in smem.
// ---------------------------------------------------------------------------
__global__ __launch_bounds__(256) void ln_proj_kernel(
    const float* __restrict__ node, const float* __restrict__ mask,
    const float* __restrict__ Wp,   const float* __restrict__ bp)
{
    extern __shared__ float sm[];
    float* Wp_s = sm;            // 16384 floats (256 x 64)
    float* xs   = sm + 16384;    // 8 x 256 normalized rows

    int t = threadIdx.x;
    // Cooperative load of W_proj (64 KB) once per block
    for (int v = t; v < 4096; v += 256)
        ((float4*)Wp_s)[v] = ((const float4*)Wp)[v];

    int w = t >> 5, lane = t & 31;
    int row = blockIdx.x * 8 + w;             // (s,i) flattened, < 49152
    const float* xr = node + (size_t)row * IN_D;

    float xv[8], s1 = 0.f, s2 = 0.f;
#pragma unroll
    for (int u = 0; u < 8; u++) {
        xv[u] = xr[lane + 32 * u];
        s1 += xv[u];
        s2 += xv[u] * xv[u];
    }
#pragma unroll
    for (int off = 16; off > 0; off >>= 1) {
        s1 += __shfl_xor_sync(0xffffffffu, s1, off);
        s2 += __shfl_xor_sync(0xffffffffu, s2, off);
    }
    float mu  = s1 * (1.f / IN_D);
    float var = s2 * (1.f / IN_D) - mu * mu;
    float rs  = rsqrtf(var + 1e-5f);

    float* xrow = xs + w * 256;
#pragma unroll
    for (int u = 0; u < 8; u++) xrow[lane + 32 * u] = (xv[u] - mu) * rs;
    __syncthreads();   // Wp_s ready (and per-warp xs rows)

    float a0 = 0.f, a1 = 0.f;
#pragma unroll 8
    for (int k = 0; k < 256; k++) {
        float xk = xrow[k];
        a0 = fmaf(xk, Wp_s[k * 64 + lane],      a0);
        a1 = fmaf(xk, Wp_s[k * 64 + lane + 32], a1);
    }
    float m  = mask[row];
    int  si  = row / I_DIM, ii = row % I_DIM;
    g_L[si * IDX + ii * PD + lane] = (a0 + bp[lane])      * m;   // l = act[..,:32]
    g_R[si * IDX + ii * PD + lane] = (a1 + bp[lane + 32]) * m;   // r = act[..,32:]
}

// ---------------------------------------------------------------------------
// Kernel B: norm[i][j] = sum_s mask[s,i]*mask[s,j]
// ---------------------------------------------------------------------------
__global__ __launch_bounds__(256) void norm_kernel(const float* __restrict__ mask)
{
    int idx = blockIdx.x * 256 + threadIdx.x;       // < 147456 exactly
    int i = idx / I_DIM, j = idx % I_DIM;
    float s = 0.f;
#pragma unroll 4
    for (int ss = 0; ss < S_DIM; ss++)
        s = fmaf(mask[ss * I_DIM + i], mask[ss * I_DIM + j], s);
    g_norm[idx] = s;
}

// ---------------------------------------------------------------------------
// Kernel C: fused pair GEMM.
// Each CTA: BI=8 i's x BJ=4 j's (32 pairs).
//  Phase 1: A[id=256][je=128] = sum_s L[s][id] * R[s][je]  (reg micro-tiles 8x8)
//  Phase 2: out[pair][f] = sum_{k=de} A[..] * W[k][f], bias + /(norm+1e-3)
// ---------------------------------------------------------------------------
#define BI 8
#define BJ 4

__global__ __launch_bounds__(512, 1) void pair_kernel(
    const float* __restrict__ W2,    // out_weights [1024][128]
    const float* __restrict__ bias,  // [128]
    float* __restrict__ out)
{
    extern __shared__ float smp[];
    float* A_s = smp;            // 256*128 floats = 128 KB
    float* aux = smp + 32768;    // 8192 floats = 32 KB (phase1 staging / phase2 W chunk)
    float* Ls  = aux;            // 16 x 256
    float* Rs  = aux + 4096;     // 16 x 128

    int t  = threadIdx.x;
    int tx = t & 31, ty = t >> 5;         // ty: 0..15
    int gi0 = blockIdx.y * BI;
    int gj0 = blockIdx.x * BJ;

    float acc[8][8];
#pragma unroll
    for (int a = 0; a < 8; a++)
#pragma unroll
        for (int b = 0; b < 8; b++) acc[a][b] = 0.f;

    const float4* Lg4 = (const float4*)g_L;
    const float4* Rg4 = (const float4*)g_R;
    float4* Ls4 = (float4*)Ls;
    float4* Rs4 = (float4*)Rs;
    int lc0 = gi0 * PD / 4;   // f4 col base in L (blockIdx.y * 64)
    int rc0 = gj0 * PD / 4;   // f4 col base in R (blockIdx.x * 32)

    // ---------------- Phase 1: GEMM1 over s ----------------
    for (int sc = 0; sc < 8; sc++) {
        int sb = sc * 16;
        __syncthreads();
        {
            int v = t;
#pragma unroll
            for (int it = 0; it < 2; it++, v += 512) {
                int ss = v >> 6, c = v & 63;
                Ls4[v] = Lg4[(sb + ss) * 3072 + lc0 + c];
            }
            int ss = t >> 5, c = t & 31;
            Rs4[t] = Rg4[(sb + ss) * 3072 + rc0 + c];
        }
        __syncthreads();
#pragma unroll
        for (int ss = 0; ss < 16; ss++) {
            float4 A0 = Ls4[ss * 64 + tx];
            float4 A1 = Ls4[ss * 64 + 32 + tx];
            float4 B0 = Rs4[ss * 32 + ty];
            float4 B1 = Rs4[ss * 32 + 16 + ty];
            float av[8] = {A0.x, A0.y, A0.z, A0.w, A1.x, A1.y, A1.z, A1.w};
            float bv[8] = {B0.x, B0.y, B0.z, B0.w, B1.x, B1.y, B1.z, B1.w};
#pragma unroll
            for (int a = 0; a < 8; a++)
#pragma unroll
                for (int b = 0; b < 8; b++)
                    acc[a][b] = fmaf(av[a], bv[b], acc[a][b]);
        }
    }
    __syncthreads();

    // Store register tile -> A_s (rows {tx*4+r, 128+tx*4+r}, cols {ty*4+c, 64+ty*4+c})
#pragma unroll
    for (int ra = 0; ra < 2; ra++)
#pragma unroll
        for (int rr = 0; rr < 4; rr++) {
            int row = ra * 128 + tx * 4 + rr;
            int ai  = ra * 4 + rr;
#pragma unroll
            for (int cb = 0; cb < 2; cb++) {
                int col = cb * 64 + ty * 4;
                *(float4*)&A_s[row * 128 + col] =
                    make_float4(acc[ai][cb * 4 + 0], acc[ai][cb * 4 + 1],
                                acc[ai][cb * 4 + 2], acc[ai][cb * 4 + 3]);
            }
        }

    // ---------------- Phase 2: contract with W ----------------
    float o0[4] = {0.f, 0.f, 0.f, 0.f};
    float o1[4] = {0.f, 0.f, 0.f, 0.f};
    int p  = t >> 4;          // pair 0..31
    int fg = t & 15;          // f group
    int pi = p >> 2, pj = p & 3;
    const float* Abase = A_s + (pi * 32) * 128 + pj * 32;
    float* W_s = aux;                       // 64 x 128 chunk
    const float4* W2g4 = (const float4*)W2;

    for (int kb = 0; kb < 16; kb++) {
        __syncthreads();
#pragma unroll
        for (int it = 0; it < 4; it++) {
            int v = t + it * 512;
            ((float4*)W_s)[v] = W2g4[kb * 2048 + v];
        }
        __syncthreads();
#pragma unroll
        for (int kl = 0; kl < 64; kl += 4) {
            int dl = kl >> 5;                 // 0/1 -> d = kb*2 + dl
            int e  = kl & 31;
            float4 a4 = *(const float4*)(Abase + (kb * 2 + dl) * 128 + e);
            float aa[4] = {a4.x, a4.y, a4.z, a4.w};
            const float* wr = W_s + kl * 128 + fg * 4;
#pragma unroll
            for (int u = 0; u < 4; u++) {
                float4 wA = *(const float4*)(wr + u * 128);
                float4 wB = *(const float4*)(wr + u * 128 + 64);
                float a = aa[u];
                o0[0] = fmaf(a, wA.x, o0[0]);
                o0[1] = fmaf(a, wA.y, o0[1]);
                o0[2] = fmaf(a, wA.z, o0[2]);
                o0[3] = fmaf(a, wA.w, o0[3]);
                o1[0] = fmaf(a, wB.x, o1[0]);
                o1[1] = fmaf(a, wB.y, o1[1]);
                o1[2] = fmaf(a, wB.z, o1[2]);
                o1[3] = fmaf(a, wB.w, o1[3]);
            }
        }
    }

    // Epilogue: bias, divide by (norm + 0.001)
    int gi = gi0 + pi, gj = gj0 + pj;
    float inv = 1.f / (g_norm[gi * I_DIM + gj] + 0.001f);
    float4 b0 = *(const float4*)(bias + fg * 4);
    float4 b1 = *(const float4*)(bias + 64 + fg * 4);
    float* orow = out + ((size_t)gi * I_DIM + gj) * OD;
    *(float4*)(orow + fg * 4) =
        make_float4((o0[0] + b0.x) * inv, (o0[1] + b0.y) * inv,
                    (o0[2] + b0.z) * inv, (o0[3] + b0.w) * inv);
    *(float4*)(orow + 64 + fg * 4) =
        make_float4((o1[0] + b1.x) * inv, (o1[1] + b1.y) * inv,
                    (o1[2] + b1.z) * inv, (o1[3] + b1.w) * inv);
}

// ---------------------------------------------------------------------------
extern "C" void kernel_launch(void* const* d_in, const int* in_sizes, int n_in,
                              void* d_out, int out_size)
{
    const float* node = (const float*)d_in[0];
    const float* mask = (const float*)d_in[1];
    const float* Wp   = (const float*)d_in[2];
    const float* bp   = (const float*)d_in[3];
    const float* W2   = (const float*)d_in[4];
    const float* bias = (const float*)d_in[5];
    float* out = (float*)d_out;

    // Idempotent, deterministic attribute sets (not stream ops; capture-safe)
    cudaFuncSetAttribute(ln_proj_kernel, cudaFuncAttributeMaxDynamicSharedMemorySize, 73728);
    cudaFuncSetAttribute(pair_kernel,    cudaFuncAttributeMaxDynamicSharedMemorySize, 163840);

    ln_proj_kernel<<<6144, 256, 73728>>>(node, mask, Wp, bp);
    norm_kernel<<<576, 256>>>(mask);
    pair_kernel<<<dim3(96, 48), 512, 163840>>>(W2, bias, out);
}